// round 2
// baseline (speedup 1.0000x reference)
#include <cuda_runtime.h>

// Shapes: x, y : (16, 64, 256, 256) fp32 ; out : (16, 256, 256) fp32
// out[b,i] = sum_c x[b,c,i] * w[b,c],  w[b,c] = sum_j y[b,c,j] / (65536*4194304)

#define NB 16
#define NC 64
#define HW 65536               // 256*256
#define HW4 (HW / 4)           // 16384 float4 per (b,c) plane
#define SCALE (1.0f / (65536.0f * 4194304.0f))  // exact: 2^-38

__device__ float g_w[NB * NC];

// ---------------- Kernel 1: reduce y over hw per (b,c) ----------------
// At ~6.6 TB/s already (measured) — unchanged.
__global__ __launch_bounds__(256) void reduce_y_kernel(const float4* __restrict__ y4) {
    const int plane = blockIdx.x;                // b*64 + c
    const float4* p = y4 + (size_t)plane * HW4;
    const int t = threadIdx.x;

    float s = 0.0f;
    #pragma unroll 8
    for (int k = 0; k < 64; ++k) {
        float4 v = __ldcs(&p[t + k * 256]);      // streaming: y read exactly once
        s += (v.x + v.y) + (v.z + v.w);
    }

    #pragma unroll
    for (int o = 16; o > 0; o >>= 1)
        s += __shfl_xor_sync(0xFFFFFFFF, s, o);

    __shared__ float smem[8];
    const int lane = t & 31, wid = t >> 5;
    if (lane == 0) smem[wid] = s;
    __syncthreads();
    if (t == 0) {
        float tot = 0.0f;
        #pragma unroll
        for (int i = 0; i < 8; ++i) tot += smem[i];
        g_w[plane] = tot * SCALE;
    }
}

// ---------------- Kernel 2: out[b,i] = sum_c x[b,c,i] * w[b,c] ----------------
// U=4 output tiling: each block owns a 1024-float4 (16KB) contiguous chunk of
// one batch's output; per c-step it reads 16KB contiguous from the c-plane
// (4x longer DRAM bursts than before -> better row locality).
// grid = 256 blocks (16 batches x 16 chunks), all co-resident in one wave.
__global__ __launch_bounds__(256) void weighted_sum_kernel(const float4* __restrict__ x4,
                                                           float4* __restrict__ out4) {
    const int blk = blockIdx.x;                  // 0..255
    const int b = blk >> 4;                      // 16 chunks per batch
    const int chunk = blk & 15;
    const int base = chunk * 1024 + threadIdx.x; // float4 index within batch

    __shared__ float w[NC];
    if (threadIdx.x < NC) w[threadIdx.x] = g_w[b * NC + threadIdx.x];
    __syncthreads();

    const float4* px = x4 + (size_t)b * NC * HW4 + base;

    float4 a0 = make_float4(0.f, 0.f, 0.f, 0.f);
    float4 a1 = make_float4(0.f, 0.f, 0.f, 0.f);
    float4 a2 = make_float4(0.f, 0.f, 0.f, 0.f);
    float4 a3 = make_float4(0.f, 0.f, 0.f, 0.f);

    #pragma unroll 2
    for (int c = 0; c < NC; ++c) {
        const float4* p = px + (size_t)c * HW4;
        float4 v0 = __ldcs(p + 0);
        float4 v1 = __ldcs(p + 256);
        float4 v2 = __ldcs(p + 512);
        float4 v3 = __ldcs(p + 768);
        const float wc = w[c];
        a0.x += v0.x * wc; a0.y += v0.y * wc; a0.z += v0.z * wc; a0.w += v0.w * wc;
        a1.x += v1.x * wc; a1.y += v1.y * wc; a1.z += v1.z * wc; a1.w += v1.w * wc;
        a2.x += v2.x * wc; a2.y += v2.y * wc; a2.z += v2.z * wc; a2.w += v2.w * wc;
        a3.x += v3.x * wc; a3.y += v3.y * wc; a3.z += v3.z * wc; a3.w += v3.w * wc;
    }

    const size_t ob = (size_t)b * HW4 + base;
    out4[ob +   0] = a0;
    out4[ob + 256] = a1;
    out4[ob + 512] = a2;
    out4[ob + 768] = a3;
}

extern "C" void kernel_launch(void* const* d_in, const int* in_sizes, int n_in,
                              void* d_out, int out_size) {
    const float4* x4 = (const float4*)d_in[0];
    const float4* y4 = (const float4*)d_in[1];
    float4* out4 = (float4*)d_out;

    reduce_y_kernel<<<NB * NC, 256>>>(y4);
    weighted_sum_kernel<<<NB * 16, 256>>>(x4, out4);
}

// round 3
// speedup vs baseline: 1.1998x; 1.1998x over previous
#include <cuda_runtime.h>

// Shapes: x, y : (16, 64, 256, 256) fp32 ; out : (16, 256, 256) fp32
// out[b,i] = sum_c x[b,c,i] * w[b,c],  w[b,c] = sum_j y[b,c,j] / (65536*4194304)
//
// Fused single kernel, 1024 blocks x 256 threads, all resident in one wave
// (launch_bounds(256,8) -> 8 blocks/SM x 148 SMs = 1184 >= 1024).
// Block blk: phase A reduces y-plane blk -> g_w[blk]; per-batch 64-block
// barrier; phase B computes output chunk blk (same batch as its plane).

#define NB 16
#define NC 64
#define HW 65536               // 256*256
#define HW4 (HW / 4)           // 16384 float4 per (b,c) plane
#define SCALE (1.0f / (65536.0f * 4194304.0f))  // exact: 2^-38

__device__ float g_w[NB * NC];
__device__ int g_cnt[NB];              // zero-init; returns to 0 every replay
__device__ unsigned int g_gen[NB];     // monotonic across replays (sense-reversing)

__global__ void __launch_bounds__(256, 8)
fused_kernel(const float4* __restrict__ x4,
             const float4* __restrict__ y4,
             float4* __restrict__ out4) {
    const int blk = blockIdx.x;            // 0..1023 == plane index b*64+c
    const int b = blk >> 6;                // batch
    const int t = threadIdx.x;

    // ---------------- Phase A: reduce y-plane blk ----------------
    {
        const float4* p = y4 + (size_t)blk * HW4;
        float s = 0.0f;
        #pragma unroll 8
        for (int k = 0; k < 64; ++k) {
            float4 v = __ldcs(&p[t + k * 256]);   // y read exactly once: stream
            s += (v.x + v.y) + (v.z + v.w);
        }
        #pragma unroll
        for (int o = 16; o > 0; o >>= 1)
            s += __shfl_xor_sync(0xFFFFFFFF, s, o);

        __shared__ float smem[8];
        if ((t & 31) == 0) smem[t >> 5] = s;
        __syncthreads();
        if (t == 0) {
            float tot = 0.0f;
            #pragma unroll
            for (int i = 0; i < 8; ++i) tot += smem[i];
            g_w[blk] = tot * SCALE;
        }
    }

    // ---------------- Per-batch barrier (64 producer blocks) ----------------
    if (t == 0) {
        __threadfence();                              // publish g_w[blk]
        unsigned my_gen = *(volatile unsigned*)&g_gen[b];  // read BEFORE arriving
        int a = atomicAdd(&g_cnt[b], 1);
        if (a == NC - 1) {
            g_cnt[b] = 0;                             // reset for next replay
            __threadfence();
            atomicAdd(&g_gen[b], 1);                  // release: wake batch
        } else {
            while (*(volatile unsigned*)&g_gen[b] == my_gen)
                __nanosleep(64);
        }
        __threadfence();                              // acquire before g_w reads
    }
    __syncthreads();

    // ---------------- Phase B: output chunk blk ----------------
    __shared__ float w[NC];
    if (t < NC) w[t] = g_w[b * NC + t];
    __syncthreads();

    const int i4 = (blk & 63) * 256 + t;              // float4 index within batch
    const float4* px = x4 + (size_t)b * NC * HW4 + i4;

    float4 acc = make_float4(0.f, 0.f, 0.f, 0.f);
    #pragma unroll 8
    for (int c = 0; c < NC; ++c) {
        float4 v = __ldcs(&px[(size_t)c * HW4]);      // x read exactly once: stream
        const float wc = w[c];
        acc.x += v.x * wc;
        acc.y += v.y * wc;
        acc.z += v.z * wc;
        acc.w += v.w * wc;
    }
    out4[(size_t)blk * 256 + t] = acc;
}

extern "C" void kernel_launch(void* const* d_in, const int* in_sizes, int n_in,
                              void* d_out, int out_size) {
    const float4* x4 = (const float4*)d_in[0];
    const float4* y4 = (const float4*)d_in[1];
    float4* out4 = (float4*)d_out;

    fused_kernel<<<NB * NC, 256>>>(x4, y4, out4);
}